// round 1
// baseline (speedup 1.0000x reference)
#include <cuda_runtime.h>
#include <cstdint>
#include <cstddef>

// ---------------------------------------------------------------------------
// Model_80985903333896: MoNet-style graph CNN.
//   B=8, M=4096, W=128, C=32, NN=16, J=4, ED=5, EMB=2
// Pipeline (7 kernels, all graph-capturable, scratch in __device__ globals):
//   K1 attn    : per-edge gaussian-mixture weights -> row softmax -> dedup
//                (last-write-wins, matching .at[].set) ; zero-init accumulators
//   K2 ygemm0  : y1 = x@l1w0^T ; y2 = x@l2w0^T + (b1+b2)   [f32x2 FMA]
//   K3 gather0 : h1 = L@y1 + y2 (16-nbr gather on C=32, L2-resident) + BN stats
//   K4 ygemm1  : BN0+relu fused on load; y1/y2 for layer 1  [f32x2 FMA]
//   K5 gather1 : h2 + BN1 stats
//   K6 fc1     : BN1+relu fused; (8,131072)@(256,131072)^T split-K, atomics
//   K7 fc2     : relu(fc1acc+b) @ fc2w^T + b -> d_out (8,53)
// ---------------------------------------------------------------------------

#define EPSBN 1e-5f
typedef unsigned long long ull;

// ------------------------- scratch (__device__ globals) --------------------
__device__ float g_w0e[65536];
__device__ float g_w1e[65536];
__device__ int   g_nbr[65536];
__device__ float g_y1[1048576];   // (B*M, 32)
__device__ float g_y2[1048576];
__device__ float g_h1[1048576];
__device__ float g_h2[1048576];
__device__ float g_sum0[32], g_sq0[32], g_sum1[32], g_sq1[32];
__device__ float g_fc1acc[2048];  // (8, 256)

// ------------------------- packed f32x2 FMA helpers ------------------------
__device__ __forceinline__ ull pk2(float x, float y) {
    ull r; asm("mov.b64 %0, {%1, %2};" : "=l"(r) : "f"(x), "f"(y)); return r;
}
__device__ __forceinline__ void ffma2(ull& d, ull a, ull b) {
    asm("fma.rn.f32x2 %0, %1, %2, %0;" : "+l"(d) : "l"(a), "l"(b));
}
__device__ __forceinline__ float2 unpk(ull v) {
    float2 r; asm("mov.b64 {%0, %1}, %2;" : "=f"(r.x), "=f"(r.y) : "l"(v)); return r;
}

// ===========================================================================
// K1: edge attention.  E = 65536 edges, 16 per row. One thread per edge.
// Softmax + dedup via 16-lane warp segments. Block 0 also zero-inits
// the BN-stat and fc1 accumulators (consumed only by later kernels).
// ===========================================================================
__global__ void __launch_bounds__(256) attn_kernel(
    const float* __restrict__ pseudo, const int* __restrict__ L_idx,
    const float* __restrict__ edge_w, const float* __restrict__ edge_b,
    const float* __restrict__ mu0, const float* __restrict__ sg0,
    const float* __restrict__ mu1, const float* __restrict__ sg1)
{
    int tid = threadIdx.x;
    if (blockIdx.x == 0) {
        if (tid < 32) {
            g_sum0[tid] = 0.f; g_sq0[tid] = 0.f;
            g_sum1[tid] = 0.f; g_sq1[tid] = 0.f;
        }
        for (int i = tid; i < 2048; i += 256) g_fc1acc[i] = 0.f;
    }
    int e = blockIdx.x * 256 + tid;
    int i = e & 15;

    float p0 = pseudo[2 * e], p1 = pseudo[2 * e + 1];
    float emb[5];
#pragma unroll
    for (int d = 0; d < 5; d++)
        emb[d] = edge_w[2 * d] * p0 + edge_w[2 * d + 1] * p1 + edge_b[d];

    float w0 = 0.f, w1 = 0.f;
#pragma unroll
    for (int j = 0; j < 4; j++) {
        float q0 = 0.f, q1 = 0.f;
#pragma unroll
        for (int d = 0; d < 5; d++) {
            float u0 = emb[d] - mu0[j * 5 + d]; q0 += u0 * u0 * sg0[j * 5 + d];
            float u1 = emb[d] - mu1[j * 5 + d]; q1 += u1 * u1 * sg1[j * 5 + d];
        }
        w0 += expf(-0.5f * q0);
        w1 += expf(-0.5f * q1);
    }

    // softmax over the 16-edge row (16-lane warp segment)
    float m0 = w0, m1 = w1;
#pragma unroll
    for (int s = 8; s; s >>= 1) {
        m0 = fmaxf(m0, __shfl_xor_sync(0xffffffffu, m0, s, 16));
        m1 = fmaxf(m1, __shfl_xor_sync(0xffffffffu, m1, s, 16));
    }
    float e0 = expf(w0 - m0), e1 = expf(w1 - m1);
    float s0 = e0, s1 = e1;
#pragma unroll
    for (int s = 8; s; s >>= 1) {
        s0 += __shfl_xor_sync(0xffffffffu, s0, s, 16);
        s1 += __shfl_xor_sync(0xffffffffu, s1, s, 16);
    }
    float a0 = e0 / s0, a1 = e1 / s1;

    // dedup: .at[].set semantics -> last duplicate index wins
    int nb = L_idx[e] & 4095;
    bool dup = false;
#pragma unroll
    for (int j = 0; j < 16; j++) {
        int nj = __shfl_sync(0xffffffffu, nb, j, 16);
        dup |= (j > i) && (nj == nb);
    }
    g_w0e[e] = dup ? 0.f : a0;
    g_w1e[e] = dup ? 0.f : a1;
    g_nbr[e] = nb;
}

// ===========================================================================
// K2/K4: projection GEMM.  rows = B*M = 32768, K = KDIM (128 or 32), 64 outs
// (y1: 32, y2: 32).  Block: 16 rows x 64 outs, 256 threads, shared tiles with
// +4 padding (33/9 odd multiples of 16B -> conflict-free float4 access).
// Warp footprint 4 rows x 8 outs; thread tile 1 row x 4 outs (stride-8).
// f32x2 packed FMA over k-pairs; two accumulators per out for ILP.
// DO_BN: source is g_h1 normalized with layer-0 BN stats + relu.
// ===========================================================================
template<int KDIM, int PADK, bool DO_BN>
__global__ void __launch_bounds__(256) ygemm_kernel(
    const float* __restrict__ xin,
    const float* __restrict__ w1, const float* __restrict__ w2,
    const float* __restrict__ b1, const float* __restrict__ b2,
    const float* __restrict__ bng, const float* __restrict__ bnb)
{
    __shared__ __align__(16) float sx[16 * PADK];
    __shared__ __align__(16) float sw[64 * PADK];
    __shared__ float s_scale[32], s_shift[32];

    int tid = threadIdx.x;
    int rowbase = blockIdx.x * 16;

    const float* src = DO_BN ? (const float*)g_h1 : xin;

    if (DO_BN && tid < 32) {
        const float inv_n = 1.0f / 32768.0f;
        float mean = g_sum0[tid] * inv_n;
        float var  = g_sq0[tid] * inv_n - mean * mean;
        float sc   = bng[tid] * rsqrtf(var + EPSBN);
        s_scale[tid] = sc;
        s_shift[tid] = bnb[tid] - mean * sc;
    }
    if (DO_BN) __syncthreads();

    for (int idx = tid; idx < 16 * KDIM; idx += 256) {
        int r = idx / KDIM, k = idx - r * KDIM;
        float v = src[rowbase * KDIM + idx];
        if (DO_BN) v = fmaxf(0.f, v * s_scale[k] + s_shift[k]);
        sx[r * PADK + k] = v;
    }
    for (int idx = tid; idx < 64 * KDIM; idx += 256) {
        int o = idx / KDIM, k = idx - o * KDIM;
        sw[o * PADK + k] = (o < 32) ? w1[o * KDIM + k] : w2[(o - 32) * KDIM + k];
    }
    __syncthreads();

    int warp = tid >> 5, lane = tid & 31;
    int wr = warp & 3, wo = warp >> 2;
    int r4 = lane >> 3, o8 = lane & 7;
    int row = wr * 4 + r4;

    ull accA[4], accB[4];
#pragma unroll
    for (int j = 0; j < 4; j++) { accA[j] = 0ull; accB[j] = 0ull; }

    const float* sxr = &sx[row * PADK];
    const float* swb = &sw[(wo * 32 + o8) * PADK];

#pragma unroll
    for (int k4 = 0; k4 < KDIM / 4; k4++) {
        float4 xv = *(const float4*)(sxr + 4 * k4);
        ull x01 = pk2(xv.x, xv.y);
        ull x23 = pk2(xv.z, xv.w);
#pragma unroll
        for (int j = 0; j < 4; j++) {
            float4 wv = *(const float4*)(swb + (8 * j) * PADK + 4 * k4);
            ffma2(accA[j], x01, pk2(wv.x, wv.y));
            ffma2(accB[j], x23, pk2(wv.z, wv.w));
        }
    }

    int grow = rowbase + row;
#pragma unroll
    for (int j = 0; j < 4; j++) {
        float2 a = unpk(accA[j]), b = unpk(accB[j]);
        float res = (a.x + a.y) + (b.x + b.y);
        int o = wo * 32 + o8 + 8 * j;
        if (o < 32) {
            g_y1[grow * 32 + o] = res;
        } else {
            int oc = o - 32;
            g_y2[grow * 32 + oc] = res + b1[oc] + b2[oc];
        }
    }
}

// ===========================================================================
// K3/K5: neighbor gather + BN stats.  One warp per (b,m) row (lane = channel),
// 4 rows per warp, 32 rows/block, 1024 blocks.  y1 is 4 MB -> pure L2 hits.
// ===========================================================================
template<int LAYER>
__global__ void __launch_bounds__(256) gather_kernel()
{
    const float* __restrict__ weff = (LAYER == 0) ? g_w0e : g_w1e;
    float* __restrict__ h   = (LAYER == 0) ? g_h1 : g_h2;
    float* gsum = (LAYER == 0) ? g_sum0 : g_sum1;
    float* gsq  = (LAYER == 0) ? g_sq0  : g_sq1;

    __shared__ float s_sum[32], s_sq[32];
    int tid = threadIdx.x, lane = tid & 31, warp = tid >> 5;
    if (tid < 32) { s_sum[tid] = 0.f; s_sq[tid] = 0.f; }
    __syncthreads();

    float lsum = 0.f, lsq = 0.f;
    int rowbase = blockIdx.x * 32 + warp * 4;
#pragma unroll
    for (int rr = 0; rr < 4; rr++) {
        int row = rowbase + rr;
        int b = row >> 12, m = row & 4095;
        float wv = 0.f; int nv = 0;
        if (lane < 16) {
            wv = weff[m * 16 + lane];
            nv = g_nbr[m * 16 + lane];
        }
        float acc = g_y2[(row << 5) + lane];
        int bb = b << 12;
#pragma unroll
        for (int i = 0; i < 16; i++) {
            float wi = __shfl_sync(0xffffffffu, wv, i);
            int   ni = __shfl_sync(0xffffffffu, nv, i);
            acc += wi * g_y1[((bb + ni) << 5) + lane];
        }
        h[(row << 5) + lane] = acc;
        lsum += acc; lsq += acc * acc;
    }
    atomicAdd(&s_sum[lane], lsum);
    atomicAdd(&s_sq[lane], lsq);
    __syncthreads();
    if (tid < 32) {
        atomicAdd(&gsum[tid], s_sum[tid]);
        atomicAdd(&gsq[tid],  s_sq[tid]);
    }
}

// ===========================================================================
// K6: fc1 with fused BN1+relu on the activation read.
// grid = 32 out-groups (8 outs) x 16 k-chunks (8192).  Block 256 threads,
// 32 k-iters; per iter: 8 weight streams (HBM) + 8 batch activations (L2),
// 64 MACs as 32 f32x2.  Shfl+shared reduce, atomicAdd to g_fc1acc.
// ===========================================================================
__global__ void __launch_bounds__(256) fc1_kernel(
    const float* __restrict__ fc1w,
    const float* __restrict__ bng, const float* __restrict__ bnb)
{
    int bx = blockIdx.x;
    int og = bx >> 4;      // 0..31
    int kc = bx & 15;      // 0..15
    int tid = threadIdx.x;

    int c = tid & 31;
    const float inv_n = 1.0f / 32768.0f;
    float mean = g_sum1[c] * inv_n;
    float var  = g_sq1[c] * inv_n - mean * mean;
    float sc   = bng[c] * rsqrtf(var + EPSBN);
    float sh   = bnb[c] - mean * sc;

    ull acc[4][8];
#pragma unroll
    for (int bp = 0; bp < 4; bp++)
#pragma unroll
        for (int j = 0; j < 8; j++) acc[bp][j] = 0ull;

    int kbase = kc * 8192 + tid;
    const float* wb = fc1w + (size_t)og * 8 * 131072;

    for (int it = 0; it < 32; it++) {
        int k = kbase + it * 256;
        float f[8];
#pragma unroll
        for (int b = 0; b < 8; b++)
            f[b] = fmaxf(0.f, fmaf(g_h2[b * 131072 + k], sc, sh));
        ull fp[4];
#pragma unroll
        for (int bp = 0; bp < 4; bp++) fp[bp] = pk2(f[2 * bp], f[2 * bp + 1]);
#pragma unroll
        for (int j = 0; j < 8; j++) {
            float w = wb[(size_t)j * 131072 + k];
            ull wp = pk2(w, w);
#pragma unroll
            for (int bp = 0; bp < 4; bp++) ffma2(acc[bp][j], fp[bp], wp);
        }
    }

    __shared__ float red[8][64];
    int lane = tid & 31, warp = tid >> 5;
#pragma unroll
    for (int bp = 0; bp < 4; bp++) {
#pragma unroll
        for (int j = 0; j < 8; j++) {
            float2 v = unpk(acc[bp][j]);
            float vlo = v.x, vhi = v.y;
#pragma unroll
            for (int s = 16; s; s >>= 1) {
                vlo += __shfl_xor_sync(0xffffffffu, vlo, s);
                vhi += __shfl_xor_sync(0xffffffffu, vhi, s);
            }
            if (lane == 0) {
                red[warp][(2 * bp) * 8 + j]     = vlo;
                red[warp][(2 * bp + 1) * 8 + j] = vhi;
            }
        }
    }
    __syncthreads();
    if (tid < 64) {
        float s = 0.f;
#pragma unroll
        for (int w = 0; w < 8; w++) s += red[w][tid];
        int b = tid >> 3, j = tid & 7;
        atomicAdd(&g_fc1acc[b * 256 + og * 8 + j], s);
    }
}

// ===========================================================================
// K7: relu(fc1acc + fc1b) @ fc2w^T + fc2b -> out (8,53). Single block.
// ===========================================================================
__global__ void __launch_bounds__(448) fc2_kernel(
    const float* __restrict__ fc1b,
    const float* __restrict__ fc2w, const float* __restrict__ fc2b,
    float* __restrict__ out)
{
    __shared__ float sf[2048];
    int tid = threadIdx.x;
    for (int i = tid; i < 2048; i += 448)
        sf[i] = fmaxf(0.f, g_fc1acc[i] + fc1b[i & 255]);
    __syncthreads();
    if (tid < 424) {
        int b = tid / 53, o = tid - b * 53;
        float acc = fc2b[o];
        const float* w = fc2w + o * 256;
        const float* f = sf + b * 256;
#pragma unroll 8
        for (int k = 0; k < 256; k++) acc += w[k] * f[k];
        out[tid] = acc;
    }
}

// ===========================================================================
extern "C" void kernel_launch(void* const* d_in, const int* in_sizes, int n_in,
                              void* d_out, int out_size)
{
    const float* x      = (const float*)d_in[0];
    const float* pseudo = (const float*)d_in[1];
    const int*   L_idx  = (const int*)  d_in[2];
    const float* edge_w = (const float*)d_in[3];
    const float* edge_b = (const float*)d_in[4];
    const float* mu0    = (const float*)d_in[5];
    const float* sg0    = (const float*)d_in[6];
    const float* mu1    = (const float*)d_in[7];
    const float* sg1    = (const float*)d_in[8];
    const float* l1w0   = (const float*)d_in[9];
    const float* l1b0   = (const float*)d_in[10];
    const float* l2w0   = (const float*)d_in[11];
    const float* l2b0   = (const float*)d_in[12];
    const float* l1w1   = (const float*)d_in[13];
    const float* l1b1   = (const float*)d_in[14];
    const float* l2w1   = (const float*)d_in[15];
    const float* l2b1   = (const float*)d_in[16];
    const float* bn_g0  = (const float*)d_in[17];
    const float* bn_b0  = (const float*)d_in[18];
    const float* bn_g1  = (const float*)d_in[19];
    const float* bn_b1  = (const float*)d_in[20];
    const float* fc1w   = (const float*)d_in[21];
    const float* fc1b   = (const float*)d_in[22];
    const float* fc2w   = (const float*)d_in[23];
    const float* fc2b   = (const float*)d_in[24];
    float* out = (float*)d_out;

    attn_kernel<<<256, 256>>>(pseudo, L_idx, edge_w, edge_b, mu0, sg0, mu1, sg1);
    ygemm_kernel<128, 132, false><<<2048, 256>>>(x, l1w0, l2w0, l1b0, l2b0, nullptr, nullptr);
    gather_kernel<0><<<1024, 256>>>();
    ygemm_kernel<32, 36, true><<<2048, 256>>>(nullptr, l1w1, l2w1, l1b1, l2b1, bn_g0, bn_b0);
    gather_kernel<1><<<1024, 256>>>();
    fc1_kernel<<<512, 256>>>(fc1w, bn_g1, bn_b1);
    fc2_kernel<<<1, 448>>>(fc1b, fc2w, fc2b, out);
}

// round 2
// speedup vs baseline: 1.4495x; 1.4495x over previous
#include <cuda_runtime.h>
#include <cstdint>
#include <cstddef>

// ---------------------------------------------------------------------------
// Model_80985903333896: MoNet-style graph CNN.
//   B=8, M=4096, W=128, C=32, NN=16, J=4, ED=5, EMB=2
// Pipeline (7 kernels):
//   K1 attn    : gaussian edge weights -> softmax -> dedup; zero accumulators
//   K2 ygemm0  : y1 = x@l1w0^T ; y2 = x@l2w0^T + b   [128x64 tile, f32x2 FMA]
//   K3 gather0 : h1 = L@y1 + y2 + BN stats
//   K4 ygemm1  : BN0+relu fused on load; layer-1 y1/y2
//   K5 gather1 : h2 + BN1 stats
//   K6 fc1     : BN1+relu fused; smem-staged acts, coalesced weight stream
//   K7 fc2     : relu(fc1acc+b) @ fc2w^T + b -> out (8,53)
// ---------------------------------------------------------------------------

#define EPSBN 1e-5f
typedef unsigned long long ull;

// ------------------------- scratch (__device__ globals) --------------------
__device__ float g_w0e[65536];
__device__ float g_w1e[65536];
__device__ int   g_nbr[65536];
__device__ float g_y1[1048576];   // (B*M, 32)
__device__ float g_y2[1048576];
__device__ float g_h1[1048576];
__device__ float g_h2[1048576];
__device__ float g_sum0[32], g_sq0[32], g_sum1[32], g_sq1[32];
__device__ float g_fc1acc[2048];  // (8, 256)

// ------------------------- packed f32x2 FMA helpers ------------------------
__device__ __forceinline__ ull pk2(float x, float y) {
    ull r; asm("mov.b64 %0, {%1, %2};" : "=l"(r) : "f"(x), "f"(y)); return r;
}
__device__ __forceinline__ void ffma2(ull& d, ull a, ull b) {
    asm("fma.rn.f32x2 %0, %1, %2, %0;" : "+l"(d) : "l"(a), "l"(b));
}
__device__ __forceinline__ float2 unpk(ull v) {
    float2 r; asm("mov.b64 {%0, %1}, %2;" : "=f"(r.x), "=f"(r.y) : "l"(v)); return r;
}

// ===========================================================================
// K1: edge attention. One thread per edge; softmax + last-write-wins dedup
// over 16-lane warp segments. Block 0 zero-inits accumulators.
// ===========================================================================
__global__ void __launch_bounds__(256) attn_kernel(
    const float* __restrict__ pseudo, const int* __restrict__ L_idx,
    const float* __restrict__ edge_w, const float* __restrict__ edge_b,
    const float* __restrict__ mu0, const float* __restrict__ sg0,
    const float* __restrict__ mu1, const float* __restrict__ sg1)
{
    int tid = threadIdx.x;
    if (blockIdx.x == 0) {
        if (tid < 32) {
            g_sum0[tid] = 0.f; g_sq0[tid] = 0.f;
            g_sum1[tid] = 0.f; g_sq1[tid] = 0.f;
        }
        for (int i = tid; i < 2048; i += 256) g_fc1acc[i] = 0.f;
    }
    int e = blockIdx.x * 256 + tid;
    int i = e & 15;

    float p0 = pseudo[2 * e], p1 = pseudo[2 * e + 1];
    float emb[5];
#pragma unroll
    for (int d = 0; d < 5; d++)
        emb[d] = edge_w[2 * d] * p0 + edge_w[2 * d + 1] * p1 + edge_b[d];

    float w0 = 0.f, w1 = 0.f;
#pragma unroll
    for (int j = 0; j < 4; j++) {
        float q0 = 0.f, q1 = 0.f;
#pragma unroll
        for (int d = 0; d < 5; d++) {
            float u0 = emb[d] - mu0[j * 5 + d]; q0 += u0 * u0 * sg0[j * 5 + d];
            float u1 = emb[d] - mu1[j * 5 + d]; q1 += u1 * u1 * sg1[j * 5 + d];
        }
        w0 += expf(-0.5f * q0);
        w1 += expf(-0.5f * q1);
    }

    float m0 = w0, m1 = w1;
#pragma unroll
    for (int s = 8; s; s >>= 1) {
        m0 = fmaxf(m0, __shfl_xor_sync(0xffffffffu, m0, s, 16));
        m1 = fmaxf(m1, __shfl_xor_sync(0xffffffffu, m1, s, 16));
    }
    float e0 = expf(w0 - m0), e1 = expf(w1 - m1);
    float s0 = e0, s1 = e1;
#pragma unroll
    for (int s = 8; s; s >>= 1) {
        s0 += __shfl_xor_sync(0xffffffffu, s0, s, 16);
        s1 += __shfl_xor_sync(0xffffffffu, s1, s, 16);
    }
    float a0 = e0 / s0, a1 = e1 / s1;

    int nb = L_idx[e] & 4095;
    bool dup = false;
#pragma unroll
    for (int j = 0; j < 16; j++) {
        int nj = __shfl_sync(0xffffffffu, nb, j, 16);
        dup |= (j > i) && (nj == nb);
    }
    g_w0e[e] = dup ? 0.f : a0;
    g_w1e[e] = dup ? 0.f : a1;
    g_nbr[e] = nb;
}

// ===========================================================================
// K2/K4: projection GEMM.  Block tile 128 rows x 64 outs, 256 threads.
// K chunked by 32 through smem (PADC=36 floats: rows 144B apart -> banks
// rotate, float4-aligned).  Thread tile 4 rows x 8 outs; warp lanes
// (r2 = lane>>3, o = lane&7): x-loads 4 unique rows (8-way bcast, 64B/instr),
// w-loads 8 unique outs (4-way bcast, 128B/instr) -> FMA-bound with f32x2.
// Epilogue staged via smem for coalesced global stores.
// ===========================================================================
template<int KDIM, bool DO_BN>
__global__ void __launch_bounds__(256, 2) ygemm_kernel(
    const float* __restrict__ xin,
    const float* __restrict__ w1, const float* __restrict__ w2,
    const float* __restrict__ b1, const float* __restrict__ b2,
    const float* __restrict__ bng, const float* __restrict__ bnb)
{
    constexpr int PADC = 36;
    __shared__ __align__(16) float s[8320];   // sx(128x36)+sw(64x36) | sout(128x65)
    __shared__ float s_scale[32], s_shift[32];
    float* sx = s;
    float* sw = s + 128 * PADC;

    int tid = threadIdx.x;
    int rowbase = blockIdx.x * 128;
    const float* src = DO_BN ? (const float*)g_h1 : xin;

    if (DO_BN) {
        if (tid < 32) {
            const float inv_n = 1.0f / 32768.0f;
            float mean = g_sum0[tid] * inv_n;
            float var  = g_sq0[tid] * inv_n - mean * mean;
            float sc   = bng[tid] * rsqrtf(var + EPSBN);
            s_scale[tid] = sc;
            s_shift[tid] = bnb[tid] - mean * sc;
        }
        __syncthreads();
    }

    int warp = tid >> 5, lane = tid & 31;
    int r2 = lane >> 3, o = lane & 7;

    ull acc[4][8];
#pragma unroll
    for (int rr = 0; rr < 4; rr++)
#pragma unroll
        for (int jj = 0; jj < 8; jj++) acc[rr][jj] = 0ull;

    constexpr int NCHUNK = KDIM / 32;
#pragma unroll
    for (int c = 0; c < NCHUNK; c++) {
        // stage x chunk: 128 rows x 32 floats (4 float4 per thread)
#pragma unroll
        for (int i = 0; i < 4; i++) {
            int idx = tid + i * 256;
            int r = idx >> 3, kq = idx & 7;
            float4 v = *(const float4*)(src + (size_t)(rowbase + r) * KDIM + c * 32 + kq * 4);
            if (DO_BN) {
                int k0 = kq * 4;   // KDIM==32 when DO_BN
                v.x = fmaxf(0.f, fmaf(v.x, s_scale[k0],     s_shift[k0]));
                v.y = fmaxf(0.f, fmaf(v.y, s_scale[k0 + 1], s_shift[k0 + 1]));
                v.z = fmaxf(0.f, fmaf(v.z, s_scale[k0 + 2], s_shift[k0 + 2]));
                v.w = fmaxf(0.f, fmaf(v.w, s_scale[k0 + 3], s_shift[k0 + 3]));
            }
            *(float4*)&sx[r * PADC + kq * 4] = v;
        }
        // stage w chunk: 64 outs x 32 floats (2 float4 per thread)
#pragma unroll
        for (int i = 0; i < 2; i++) {
            int idx = tid + i * 256;
            int oo = idx >> 3, kq = idx & 7;
            const float* wsrc = (oo < 32) ? (w1 + oo * KDIM) : (w2 + (oo - 32) * KDIM);
            *(float4*)&sw[oo * PADC + kq * 4] = *(const float4*)(wsrc + c * 32 + kq * 4);
        }
        __syncthreads();

#pragma unroll
        for (int kk = 0; kk < 8; kk++) {
            ull x01[4], x23[4];
#pragma unroll
            for (int rr = 0; rr < 4; rr++) {
                float4 xv = *(const float4*)&sx[(warp * 16 + rr * 4 + r2) * PADC + kk * 4];
                x01[rr] = pk2(xv.x, xv.y);
                x23[rr] = pk2(xv.z, xv.w);
            }
#pragma unroll
            for (int jj = 0; jj < 8; jj++) {
                float4 wv = *(const float4*)&sw[(o + 8 * jj) * PADC + kk * 4];
                ull w01 = pk2(wv.x, wv.y), w23 = pk2(wv.z, wv.w);
#pragma unroll
                for (int rr = 0; rr < 4; rr++) {
                    ffma2(acc[rr][jj], x01[rr], w01);
                    ffma2(acc[rr][jj], x23[rr], w23);
                }
            }
        }
        __syncthreads();
    }

    // epilogue: stage into smem (row stride 65), then coalesced stores
#pragma unroll
    for (int rr = 0; rr < 4; rr++)
#pragma unroll
        for (int jj = 0; jj < 8; jj++) {
            float2 v = unpk(acc[rr][jj]);
            s[(warp * 16 + rr * 4 + r2) * 65 + (o + 8 * jj)] = v.x + v.y;
        }
    __syncthreads();

#pragma unroll
    for (int i = 0; i < 8; i++) {
        int idx = tid + i * 256;         // 2048 float4 = 128 rows x 16
        int r = idx >> 4, q = idx & 15;
        int c0 = q * 4;
        float4 v;
        v.x = s[r * 65 + c0];
        v.y = s[r * 65 + c0 + 1];
        v.z = s[r * 65 + c0 + 2];
        v.w = s[r * 65 + c0 + 3];
        int grow = rowbase + r;
        if (c0 < 32) {
            *(float4*)&g_y1[grow * 32 + c0] = v;
        } else {
            int oc = c0 - 32;
            v.x += b1[oc]     + b2[oc];
            v.y += b1[oc + 1] + b2[oc + 1];
            v.z += b1[oc + 2] + b2[oc + 2];
            v.w += b1[oc + 3] + b2[oc + 3];
            *(float4*)&g_y2[grow * 32 + oc] = v;
        }
    }
}

// ===========================================================================
// K3/K5: neighbor gather + BN stats. One warp per row (lane = channel),
// 4 rows per warp; g_y1 is 4 MB -> L2 resident.
// ===========================================================================
template<int LAYER>
__global__ void __launch_bounds__(256) gather_kernel()
{
    const float* __restrict__ weff = (LAYER == 0) ? g_w0e : g_w1e;
    float* __restrict__ h   = (LAYER == 0) ? g_h1 : g_h2;
    float* gsum = (LAYER == 0) ? g_sum0 : g_sum1;
    float* gsq  = (LAYER == 0) ? g_sq0  : g_sq1;

    __shared__ float s_sum[32], s_sq[32];
    int tid = threadIdx.x, lane = tid & 31, warp = tid >> 5;
    if (tid < 32) { s_sum[tid] = 0.f; s_sq[tid] = 0.f; }
    __syncthreads();

    float lsum = 0.f, lsq = 0.f;
    int rowbase = blockIdx.x * 32 + warp * 4;
#pragma unroll
    for (int rr = 0; rr < 4; rr++) {
        int row = rowbase + rr;
        int b = row >> 12, m = row & 4095;
        float wv = 0.f; int nv = 0;
        if (lane < 16) {
            wv = weff[m * 16 + lane];
            nv = g_nbr[m * 16 + lane];
        }
        float acc = g_y2[(row << 5) + lane];
        int bb = b << 12;
#pragma unroll
        for (int i = 0; i < 16; i++) {
            float wi = __shfl_sync(0xffffffffu, wv, i);
            int   ni = __shfl_sync(0xffffffffu, nv, i);
            acc += wi * g_y1[((bb + ni) << 5) + lane];
        }
        h[(row << 5) + lane] = acc;
        lsum += acc; lsq += acc * acc;
    }
    atomicAdd(&s_sum[lane], lsum);
    atomicAdd(&s_sq[lane], lsq);
    __syncthreads();
    if (tid < 32) {
        atomicAdd(&gsum[tid], s_sum[tid]);
        atomicAdd(&gsq[tid],  s_sq[tid]);
    }
}

// ===========================================================================
// K6: fc1, BN1+relu fused.  grid = 8 out-groups(32 outs) x 128 k-chunks(1024).
// Acts staged once per block into smem (L2 act traffic 134MB -> 32MB);
// weights streamed coalesced float4 (134 MB HBM, read once).
// Warp = 4 outs; per iter: 4 LDG.128 (w) + 8 LDS.128 (acts) + 128 FMA.
// Lane-reduction via padded smem transpose; atomicAdd into g_fc1acc.
// ===========================================================================
__global__ void __launch_bounds__(256, 2) fc1_kernel(
    const float* __restrict__ fc1w,
    const float* __restrict__ bng, const float* __restrict__ bnb)
{
    __shared__ __align__(16) float s_act[8448];  // acts 8x1024 | red 256x33
    __shared__ float s_sc[32], s_sh[32];

    int tid = threadIdx.x;
    int og = blockIdx.x >> 7;        // 0..7  (32 outs each)
    int kc = blockIdx.x & 127;       // 0..127 (1024 k each)
    int kbase = kc * 1024;

    if (tid < 32) {
        const float inv_n = 1.0f / 32768.0f;
        float mean = g_sum1[tid] * inv_n;
        float var  = g_sq1[tid] * inv_n - mean * mean;
        float sc   = bng[tid] * rsqrtf(var + EPSBN);
        s_sc[tid] = sc;
        s_sh[tid] = bnb[tid] - mean * sc;
    }
    __syncthreads();

    // stage activations with BN+relu: 8 batches x 1024 k
#pragma unroll
    for (int i = 0; i < 8; i++) {
        int idx = tid + i * 256;
        int b = idx >> 8, kq = idx & 255;
        float4 v = *(const float4*)(g_h2 + b * 131072 + kbase + kq * 4);
        int c0 = (kq * 4) & 31;
        v.x = fmaxf(0.f, fmaf(v.x, s_sc[c0],     s_sh[c0]));
        v.y = fmaxf(0.f, fmaf(v.y, s_sc[c0 + 1], s_sh[c0 + 1]));
        v.z = fmaxf(0.f, fmaf(v.z, s_sc[c0 + 2], s_sh[c0 + 2]));
        v.w = fmaxf(0.f, fmaf(v.w, s_sc[c0 + 3], s_sh[c0 + 3]));
        *(float4*)&s_act[b * 1024 + kq * 4] = v;
    }
    __syncthreads();

    int warp = tid >> 5, lane = tid & 31;
    const float* wb = fc1w + (size_t)(og * 32 + warp * 4) * 131072 + kbase;

    float acc[4][8];
#pragma unroll
    for (int jj = 0; jj < 4; jj++)
#pragma unroll
        for (int b = 0; b < 8; b++) acc[jj][b] = 0.f;

#pragma unroll
    for (int it = 0; it < 8; it++) {
        int k0 = it * 128 + lane * 4;
        float4 a[8];
#pragma unroll
        for (int b = 0; b < 8; b++)
            a[b] = *(const float4*)&s_act[b * 1024 + k0];
#pragma unroll
        for (int jj = 0; jj < 4; jj++) {
            float4 w = *(const float4*)(wb + (size_t)jj * 131072 + k0);
#pragma unroll
            for (int b = 0; b < 8; b++) {
                float t = acc[jj][b];
                t = fmaf(w.x, a[b].x, t);
                t = fmaf(w.y, a[b].y, t);
                t = fmaf(w.z, a[b].z, t);
                t = fmaf(w.w, a[b].w, t);
                acc[jj][b] = t;
            }
        }
    }
    __syncthreads();   // done with act region

    // transpose-reduce across lanes via padded smem
#pragma unroll
    for (int jj = 0; jj < 4; jj++)
#pragma unroll
        for (int b = 0; b < 8; b++)
            s_act[(warp * 32 + jj * 8 + b) * 33 + lane] = acc[jj][b];
    __syncthreads();

    float s = 0.f;
#pragma unroll
    for (int l = 0; l < 32; l++) s += s_act[tid * 33 + l];
    int wg = tid >> 5, jj = (tid >> 3) & 3, b = tid & 7;
    atomicAdd(&g_fc1acc[b * 256 + og * 32 + wg * 4 + jj], s);
}

// ===========================================================================
// K7: relu(fc1acc + fc1b) @ fc2w^T + fc2b -> out (8,53). Single block.
// ===========================================================================
__global__ void __launch_bounds__(448) fc2_kernel(
    const float* __restrict__ fc1b,
    const float* __restrict__ fc2w, const float* __restrict__ fc2b,
    float* __restrict__ out)
{
    __shared__ float sf[2048];
    int tid = threadIdx.x;
    for (int i = tid; i < 2048; i += 448)
        sf[i] = fmaxf(0.f, g_fc1acc[i] + fc1b[i & 255]);
    __syncthreads();
    if (tid < 424) {
        int b = tid / 53, o = tid - b * 53;
        float acc = fc2b[o];
        const float* w = fc2w + o * 256;
        const float* f = sf + b * 256;
#pragma unroll 8
        for (int k = 0; k < 256; k++) acc += w[k] * f[k];
        out[tid] = acc;
    }
}

// ===========================================================================
extern "C" void kernel_launch(void* const* d_in, const int* in_sizes, int n_in,
                              void* d_out, int out_size)
{
    const float* x      = (const float*)d_in[0];
    const float* pseudo = (const float*)d_in[1];
    const int*   L_idx  = (const int*)  d_in[2];
    const float* edge_w = (const float*)d_in[3];
    const float* edge_b = (const float*)d_in[4];
    const float* mu0    = (const float*)d_in[5];
    const float* sg0    = (const float*)d_in[6];
    const float* mu1    = (const float*)d_in[7];
    const float* sg1    = (const float*)d_in[8];
    const float* l1w0   = (const float*)d_in[9];
    const float* l1b0   = (const float*)d_in[10];
    const float* l2w0   = (const float*)d_in[11];
    const float* l2b0   = (const float*)d_in[12];
    const float* l1w1   = (const float*)d_in[13];
    const float* l1b1   = (const float*)d_in[14];
    const float* l2w1   = (const float*)d_in[15];
    const float* l2b1   = (const float*)d_in[16];
    const float* bn_g0  = (const float*)d_in[17];
    const float* bn_b0  = (const float*)d_in[18];
    const float* bn_g1  = (const float*)d_in[19];
    const float* bn_b1  = (const float*)d_in[20];
    const float* fc1w   = (const float*)d_in[21];
    const float* fc1b   = (const float*)d_in[22];
    const float* fc2w   = (const float*)d_in[23];
    const float* fc2b   = (const float*)d_in[24];
    float* out = (float*)d_out;

    attn_kernel<<<256, 256>>>(pseudo, L_idx, edge_w, edge_b, mu0, sg0, mu1, sg1);
    ygemm_kernel<128, false><<<256, 256>>>(x, l1w0, l2w0, l1b0, l2b0, nullptr, nullptr);
    gather_kernel<0><<<1024, 256>>>();
    ygemm_kernel<32, true><<<256, 256>>>(nullptr, l1w1, l2w1, l1b1, l2b1, bn_g0, bn_b0);
    gather_kernel<1><<<1024, 256>>>();
    fc1_kernel<<<1024, 256>>>(fc1w, bn_g1, bn_b1);
    fc2_kernel<<<1, 448>>>(fc1b, fc2w, fc2b, out);
}